// round 16
// baseline (speedup 1.0000x reference)
#include <cuda_runtime.h>
#include <math.h>
#include <stdint.h>

// Problem shape (fixed by the reference): B=64, T=2048, D=U=256.
#define B_     64
#define T_     2048
#define D_     256
#define NCHUNK 8                 // T-chunks per batch row -> grid 512, one wave
#define TCHUNK (T_ / NCHUNK)     // 256 t-rows per block
#define TSUB   16                // rows per SMEM subtile (16 KB)
#define NSUB   (TCHUNK / TSUB)   // 16 subtiles
#define NBUF   3                 // pipeline depth (2 tiles in flight)
#define TILE_BYTES (TSUB * D_ * 4)   // 16384

// Scratch (allocation-free rule -> __device__ globals)
__device__ float g_w[D_];                       // w = W @ v
__device__ float g_pz[B_ * NCHUNK];             // per-chunk sum(exp)   [shift 0]
__device__ float g_pacc[B_ * NCHUNK * D_];      // per-chunk weighted accumulators

// ---------------------------------------------------------------------------
// TMA bulk + mbarrier helpers
// ---------------------------------------------------------------------------
__device__ __forceinline__ void mbar_init(uint32_t mbar, uint32_t count) {
    asm volatile("mbarrier.init.shared.b64 [%0], %1;" :: "r"(mbar), "r"(count) : "memory");
}
__device__ __forceinline__ void mbar_expect_tx(uint32_t mbar, uint32_t bytes) {
    asm volatile("mbarrier.arrive.expect_tx.shared.b64 _, [%0], %1;"
                 :: "r"(mbar), "r"(bytes) : "memory");
}
__device__ __forceinline__ void cp_bulk(uint32_t dst_smem, const void* src,
                                        uint32_t bytes, uint32_t mbar) {
    asm volatile("cp.async.bulk.shared::cta.global.mbarrier::complete_tx::bytes "
                 "[%0], [%1], %2, [%3];"
                 :: "r"(dst_smem), "l"(src), "r"(bytes), "r"(mbar) : "memory");
}
__device__ __forceinline__ void mbar_wait(uint32_t mbar, uint32_t parity) {
    asm volatile(
        "{\n\t.reg .pred P;\n\t"
        "W_%=:\n\t"
        "mbarrier.try_wait.parity.acquire.cta.shared::cta.b64 P, [%0], %1, 0x989680;\n\t"
        "@!P bra W_%=;\n\t}"
        :: "r"(mbar), "r"(parity) : "memory");
}
__device__ __forceinline__ void fence_proxy_async_cta() {
    asm volatile("fence.proxy.async.shared::cta;" ::: "memory");
}

// ---------------------------------------------------------------------------
// Kernel 1: w[d] = sum_u W[d,u] * v[u].  64 blocks x 128 threads, warp-per-row.
// Fires PDL completion at entry so k_chunk's tile-0 loads co-start.
// ---------------------------------------------------------------------------
__global__ void k_wv(const float* __restrict__ W, const float* __restrict__ v) {
    cudaTriggerProgrammaticLaunchCompletion();

    const int lane = threadIdx.x & 31;
    const int warp = threadIdx.x >> 5;
    const int r = blockIdx.x * 4 + warp;           // 64*4 = 256 rows

    const float4* v4 = (const float4*)v;
    const float4 va = v4[lane];
    const float4 vb = v4[32 + lane];

    const float4* row = (const float4*)(W + r * D_);
    const float4 xa = row[lane];
    const float4 xb = row[32 + lane];
    float s = xa.x * va.x + xa.y * va.y + xa.z * va.z + xa.w * va.w
            + xb.x * vb.x + xb.y * vb.y + xb.z * vb.z + xb.w * vb.w;
    #pragma unroll
    for (int o = 16; o > 0; o >>= 1) s += __shfl_xor_sync(0xffffffffu, s, o);
    if (lane == 0) g_w[r] = s;
}

// ---------------------------------------------------------------------------
// Kernel 2: fused scores + shift-free softmax + register accumulation.
// One block per (b, chunk); 512 blocks = one wave at 4 blocks/SM.
// Tile loads use TMA BULK copies (one UBLKCP per 16 KB tile, issued by one
// thread into a per-buffer mbarrier) instead of 1024 LDGSTS: the transfer
// rides the dedicated bulk engine, leaving the LSU/L1tex issue path entirely
// to the consumer warps' LDS traffic. Buffer recycling safety is unchanged:
// tile s+2 is issued only after the post-wait __syncthreads for tile s, by
// which point every thread has finished reading buffer (s-1)%3 = (s+2)%3.
// ---------------------------------------------------------------------------
__global__ __launch_bounds__(256, 4) void k_chunk(const float* __restrict__ x) {
    __shared__ alignas(128) float sx[NBUF][TSUB * D_];  // 3 x 16 KB tiles
    __shared__ alignas(8) uint64_t mbar_s[NBUF];        // per-buffer full barriers
    __shared__ float s_z[8];                            // per-warp Z (end merge)

    const int tid  = threadIdx.x;
    const int lane = tid & 31;
    const int warp = tid >> 5;
    const int b = blockIdx.y;
    const int c = blockIdx.x;

    const size_t base = ((size_t)b * T_ + (size_t)c * TCHUNK) * D_;

    uint32_t sb[NBUF], mb[NBUF];
    #pragma unroll
    for (int i = 0; i < NBUF; i++) {
        sb[i] = (uint32_t)__cvta_generic_to_shared(&sx[i][0]);
        mb[i] = (uint32_t)__cvta_generic_to_shared(&mbar_s[i]);
    }

    // init barriers (count=1: the producer's arrive.expect_tx)
    if (tid == 0) {
        #pragma unroll
        for (int i = 0; i < NBUF; i++) mbar_init(mb[i], 1);
        fence_proxy_async_cta();
    }
    __syncthreads();

    // issue tile s into buffer buf: ONE bulk copy from one thread
    auto issue_tile = [&](int s, int buf) {
        if (tid == 0) {
            mbar_expect_tx(mb[buf], TILE_BYTES);
            cp_bulk(sb[buf], x + base + (size_t)s * TSUB * D_, TILE_BYTES, mb[buf]);
        }
    };

    // Tiles 0,1 do not depend on w -> issue before waiting for k_wv.
    issue_tile(0, 0);
    issue_tile(1, 1);

    cudaGridDependencySynchronize();           // k_wv done; g_w valid
    const float4* w4 = (const float4*)g_w;
    const float4 wa = w4[lane];
    const float4 wb = w4[32 + lane];

    float Zw = 0.0f;       // this warp's partial sum-exp (shift 0)
    // per-warp partial output: lane holds dims {4*lane+k} and {128+4*lane+k}
    float accA[4] = {0.f, 0.f, 0.f, 0.f};
    float accB[4] = {0.f, 0.f, 0.f, 0.f};

    const int r0 = warp * 2;       // this warp's two rows in every subtile
    const int r1 = warp * 2 + 1;

    for (int s = 0; s < NSUB; s++) {
        const int cur = s % NBUF;

        mbar_wait(mb[cur], (s / NBUF) & 1);   // tile s landed (TMA complete_tx)
        __syncthreads();        // every thread past iteration s-1 -> buffer
                                // (s+2)%3 fully consumed, safe to re-fill

        if (s + 2 < NSUB) issue_tile(s + 2, (s + 2) % NBUF);  // overlaps compute

        // ---- load this warp's 2 rows into registers + dot ----
        const float* tile = &sx[cur][0];
        const float4* q0 = (const float4*)(tile + r0 * D_);
        const float4* q1 = (const float4*)(tile + r1 * D_);
        const float4 xa0 = q0[lane],      xb0 = q0[32 + lane];
        const float4 xa1 = q1[lane],      xb1 = q1[32 + lane];

        float sc0 = xa0.x * wa.x + xa0.y * wa.y + xa0.z * wa.z + xa0.w * wa.w
                  + xb0.x * wb.x + xb0.y * wb.y + xb0.z * wb.z + xb0.w * wb.w;
        float sc1 = xa1.x * wa.x + xa1.y * wa.y + xa1.z * wa.z + xa1.w * wa.w
                  + xb1.x * wb.x + xb1.y * wb.y + xb1.z * wb.z + xb1.w * wb.w;
        #pragma unroll
        for (int o = 16; o > 0; o >>= 1) {
            sc0 += __shfl_xor_sync(0xffffffffu, sc0, o);
            sc1 += __shfl_xor_sync(0xffffffffu, sc1, o);
        }

        // ---- shift-free softmax weights + accumulation (pure FMA) ----
        const float p0 = __expf(sc0);
        const float p1 = __expf(sc1);
        Zw += p0 + p1;

        accA[0] = fmaf(p0, xa0.x, accA[0]);  accA[1] = fmaf(p0, xa0.y, accA[1]);
        accA[2] = fmaf(p0, xa0.z, accA[2]);  accA[3] = fmaf(p0, xa0.w, accA[3]);
        accB[0] = fmaf(p0, xb0.x, accB[0]);  accB[1] = fmaf(p0, xb0.y, accB[1]);
        accB[2] = fmaf(p0, xb0.z, accB[2]);  accB[3] = fmaf(p0, xb0.w, accB[3]);
        accA[0] = fmaf(p1, xa1.x, accA[0]);  accA[1] = fmaf(p1, xa1.y, accA[1]);
        accA[2] = fmaf(p1, xa1.z, accA[2]);  accA[3] = fmaf(p1, xa1.w, accA[3]);
        accB[0] = fmaf(p1, xb1.x, accB[0]);  accB[1] = fmaf(p1, xb1.y, accB[1]);
        accB[2] = fmaf(p1, xb1.z, accB[2]);  accB[3] = fmaf(p1, xb1.w, accB[3]);
    }

    // ---- merge the 8 warp partials (plain sums; common shift 0) ----
    if (lane == 0) s_z[warp] = Zw;
    __syncthreads();            // all warps past last tile reads

    float* sacc = &sx[0][0];    // tile buffers free after the barrier above
    ((float4*)(sacc + warp * D_))[lane] =
        make_float4(accA[0], accA[1], accA[2], accA[3]);
    ((float4*)(sacc + warp * D_ + 128))[lane] =
        make_float4(accB[0], accB[1], accB[2], accB[3]);
    __syncthreads();

    float o = 0.0f;
    #pragma unroll
    for (int w = 0; w < 8; w++) o += sacc[w * D_ + tid];

    const int idx = b * NCHUNK + c;
    g_pacc[(size_t)idx * D_ + tid] = o;
    if (tid == 0) {
        float Z = 0.0f;
        #pragma unroll
        for (int w = 0; w < 8; w++) Z += s_z[w];
        g_pz[idx] = Z;
    }
}

// ---------------------------------------------------------------------------
// Kernel 3: merge the NCHUNK chunk partials per batch row, write out[b, d].
// All chunks share softmax shift 0 -> merge is a plain sum.
// PDL: launches early, waits for k_chunk's grid in-kernel.
// ---------------------------------------------------------------------------
__global__ void k_merge(float* __restrict__ out) {
    cudaGridDependencySynchronize();

    const int b = blockIdx.x;
    const int tid = threadIdx.x;

    float Z = 0.0f, o = 0.0f;
    #pragma unroll
    for (int c = 0; c < NCHUNK; c++) {
        Z += g_pz[b * NCHUNK + c];
        o += g_pacc[(size_t)(b * NCHUNK + c) * D_ + tid];
    }
    out[b * D_ + tid] = o / Z;
}

// ---------------------------------------------------------------------------
// Inputs (metadata order): 0:x 1:g 2:W 3:Wg 4:b 5:v
// g, Wg, b are provably dead (softmax shift invariance).
// ---------------------------------------------------------------------------
extern "C" void kernel_launch(void* const* d_in, const int* in_sizes, int n_in,
                              void* d_out, int out_size) {
    const float* x = (const float*)d_in[0];
    const float* W = (const float*)d_in[2];
    const float* v = (const float*)d_in[5];
    float* out = (float*)d_out;

    k_wv<<<64, 128>>>(W, v);

    cudaLaunchAttribute pdl[1];
    pdl[0].id = cudaLaunchAttributeProgrammaticStreamSerialization;
    pdl[0].val.programmaticStreamSerializationAllowed = 1;

    cudaLaunchConfig_t cfg1 = {};
    cfg1.gridDim  = dim3(NCHUNK, B_);
    cfg1.blockDim = dim3(256);
    cfg1.stream = 0;
    cfg1.attrs = pdl;
    cfg1.numAttrs = 1;
    cudaLaunchKernelEx(&cfg1, k_chunk, x);

    cudaLaunchConfig_t cfg2 = {};
    cfg2.gridDim  = dim3(B_);
    cfg2.blockDim = dim3(256);
    cfg2.stream = 0;
    cfg2.attrs = pdl;
    cfg2.numAttrs = 1;
    cudaLaunchKernelEx(&cfg2, k_merge, out);
}

// round 17
// speedup vs baseline: 1.0647x; 1.0647x over previous
#include <cuda_runtime.h>
#include <math.h>
#include <stdint.h>

// Problem shape (fixed by the reference): B=64, T=2048, D=U=256.
#define B_     64
#define T_     2048
#define D_     256
#define NCHUNK 8                 // T-chunks per batch row -> grid 512, one wave
#define TCHUNK (T_ / NCHUNK)     // 256 t-rows per block
#define TSUB   16                // rows per SMEM subtile (16 KB)
#define NSUB   (TCHUNK / TSUB)   // 16 subtiles
#define NBUF   3                 // cp.async pipeline depth (2 groups in flight)

// Scratch (allocation-free rule -> __device__ globals)
__device__ float g_w[D_];                       // w = W @ v
__device__ float g_pz[B_ * NCHUNK];             // per-chunk sum(exp)   [shift 0]
__device__ float g_pacc[B_ * NCHUNK * D_];      // per-chunk weighted accumulators

// ---------------------------------------------------------------------------
// cp.async helpers (LDGSTS on sm_103a)
// ---------------------------------------------------------------------------
__device__ __forceinline__ void cp_async16(uint32_t smem_addr, const void* gptr) {
    asm volatile("cp.async.cg.shared.global [%0], [%1], 16;\n"
                 :: "r"(smem_addr), "l"(gptr) : "memory");
}
__device__ __forceinline__ void cp_commit() {
    asm volatile("cp.async.commit_group;\n" ::: "memory");
}
__device__ __forceinline__ void cp_wait1() {   // newest group may stay in flight
    asm volatile("cp.async.wait_group 1;\n" ::: "memory");
}
__device__ __forceinline__ void cp_wait0() {   // drain everything
    asm volatile("cp.async.wait_group 0;\n" ::: "memory");
}

// ---------------------------------------------------------------------------
// Kernel 1: w[d] = sum_u W[d,u] * v[u].  64 blocks x 128 threads, warp-per-row.
// Fires PDL completion at entry so k_chunk's tile-0 loads co-start.
// ---------------------------------------------------------------------------
__global__ void k_wv(const float* __restrict__ W, const float* __restrict__ v) {
    cudaTriggerProgrammaticLaunchCompletion();

    const int lane = threadIdx.x & 31;
    const int warp = threadIdx.x >> 5;
    const int r = blockIdx.x * 4 + warp;           // 64*4 = 256 rows

    const float4* v4 = (const float4*)v;
    const float4 va = v4[lane];
    const float4 vb = v4[32 + lane];

    const float4* row = (const float4*)(W + r * D_);
    const float4 xa = row[lane];
    const float4 xb = row[32 + lane];
    float s = xa.x * va.x + xa.y * va.y + xa.z * va.z + xa.w * va.w
            + xb.x * vb.x + xb.y * vb.y + xb.z * vb.z + xb.w * vb.w;
    #pragma unroll
    for (int o = 16; o > 0; o >>= 1) s += __shfl_xor_sync(0xffffffffu, s, o);
    if (lane == 0) g_w[r] = s;
}

// ---------------------------------------------------------------------------
// Kernel 2: fused scores + shift-free softmax + register accumulation.
// One block per (b, chunk); 512 blocks = one wave at 4 blocks/SM.
// Before the PDL grid-sync on k_wv the block issues its first two tiles via
// cp.async AND prefetch.global.L2 for tiles 2-5 (64 KB): the prefetches
// stream x into L2 during the otherwise-idle k_wv wait window, so the first
// post-sync tiles are L2 hits instead of DRAM misses.
// 3-stage cp.async pipeline keeps 2 tiles (32 KB/block) in DRAM flight.
// ---------------------------------------------------------------------------
__global__ __launch_bounds__(256, 4) void k_chunk(const float* __restrict__ x) {
    __shared__ float sx[NBUF][TSUB * D_];   // 3 x 16 KB tiles (buf reused at end)
    __shared__ float s_z[8];                // per-warp Z (end merge)

    const int tid  = threadIdx.x;
    const int lane = tid & 31;
    const int warp = tid >> 5;
    const int b = blockIdx.y;
    const int c = blockIdx.x;

    const size_t base = ((size_t)b * T_ + (size_t)c * TCHUNK) * D_;

    uint32_t sb[NBUF];
    #pragma unroll
    for (int i = 0; i < NBUF; i++)
        sb[i] = (uint32_t)__cvta_generic_to_shared(&sx[i][0]);

    // issue tile s into buffer buf (4 x 16B per thread = 16 KB total)
    auto issue_tile = [&](int s, int buf) {
        const float4* gx = (const float4*)(x + base + (size_t)s * TSUB * D_);
        #pragma unroll
        for (int i = 0; i < 4; i++)
            cp_async16(sb[buf] + (uint32_t)(i * 256 + tid) * 16u, gx + i * 256 + tid);
        cp_commit();
    };

    // Tiles 0,1 do not depend on w -> issue before waiting for k_wv.
    issue_tile(0, 0);
    issue_tile(1, 1);

    // L2 prefetch of tiles 2..5 (512 x 128B lines, 2 per thread): streams
    // under the PDL wait below, warming L2 for the first post-sync tiles.
    {
        const float* pf = x + base + (size_t)2 * TSUB * D_;   // start of tile 2
        #pragma unroll
        for (int i = 0; i < 2; i++)
            asm volatile("prefetch.global.L2 [%0];"
                         :: "l"(pf + (size_t)(i * 256 + tid) * 32) : "memory");
    }

    cudaGridDependencySynchronize();           // k_wv done; g_w valid
    const float4* w4 = (const float4*)g_w;
    const float4 wa = w4[lane];
    const float4 wb = w4[32 + lane];

    float Zw = 0.0f;       // this warp's partial sum-exp (shift 0)
    // per-warp partial output: lane holds dims {4*lane+k} and {128+4*lane+k}
    float accA[4] = {0.f, 0.f, 0.f, 0.f};
    float accB[4] = {0.f, 0.f, 0.f, 0.f};

    const int r0 = warp * 2;       // this warp's two rows in every subtile
    const int r1 = warp * 2 + 1;

    for (int s = 0; s < NSUB; s++) {
        const int cur = s % NBUF;

        if (s + 1 < NSUB) cp_wait1(); else cp_wait0();   // tile s resident
        __syncthreads();        // publish tile s block-wide; buffer (s-1)%NBUF
                                // fully consumed by everyone

        if (s + 2 < NSUB) issue_tile(s + 2, (s + 2) % NBUF);  // overlaps compute

        // ---- load this warp's 2 rows into registers + dot ----
        const float* tile = &sx[cur][0];
        const float4* q0 = (const float4*)(tile + r0 * D_);
        const float4* q1 = (const float4*)(tile + r1 * D_);
        const float4 xa0 = q0[lane],      xb0 = q0[32 + lane];
        const float4 xa1 = q1[lane],      xb1 = q1[32 + lane];

        float sc0 = xa0.x * wa.x + xa0.y * wa.y + xa0.z * wa.z + xa0.w * wa.w
                  + xb0.x * wb.x + xb0.y * wb.y + xb0.z * wb.z + xb0.w * wb.w;
        float sc1 = xa1.x * wa.x + xa1.y * wa.y + xa1.z * wa.z + xa1.w * wa.w
                  + xb1.x * wb.x + xb1.y * wb.y + xb1.z * wb.z + xb1.w * wb.w;
        #pragma unroll
        for (int o = 16; o > 0; o >>= 1) {
            sc0 += __shfl_xor_sync(0xffffffffu, sc0, o);
            sc1 += __shfl_xor_sync(0xffffffffu, sc1, o);
        }

        // ---- shift-free softmax weights + accumulation (pure FMA) ----
        const float p0 = __expf(sc0);
        const float p1 = __expf(sc1);
        Zw += p0 + p1;

        accA[0] = fmaf(p0, xa0.x, accA[0]);  accA[1] = fmaf(p0, xa0.y, accA[1]);
        accA[2] = fmaf(p0, xa0.z, accA[2]);  accA[3] = fmaf(p0, xa0.w, accA[3]);
        accB[0] = fmaf(p0, xb0.x, accB[0]);  accB[1] = fmaf(p0, xb0.y, accB[1]);
        accB[2] = fmaf(p0, xb0.z, accB[2]);  accB[3] = fmaf(p0, xb0.w, accB[3]);
        accA[0] = fmaf(p1, xa1.x, accA[0]);  accA[1] = fmaf(p1, xa1.y, accA[1]);
        accA[2] = fmaf(p1, xa1.z, accA[2]);  accA[3] = fmaf(p1, xa1.w, accA[3]);
        accB[0] = fmaf(p1, xb1.x, accB[0]);  accB[1] = fmaf(p1, xb1.y, accB[1]);
        accB[2] = fmaf(p1, xb1.z, accB[2]);  accB[3] = fmaf(p1, xb1.w, accB[3]);
    }

    // ---- merge the 8 warp partials (plain sums; common shift 0) ----
    if (lane == 0) s_z[warp] = Zw;
    __syncthreads();            // all warps past last tile reads

    float* sacc = &sx[0][0];    // tile buffers free after the barrier above
    ((float4*)(sacc + warp * D_))[lane] =
        make_float4(accA[0], accA[1], accA[2], accA[3]);
    ((float4*)(sacc + warp * D_ + 128))[lane] =
        make_float4(accB[0], accB[1], accB[2], accB[3]);
    __syncthreads();

    float o = 0.0f;
    #pragma unroll
    for (int w = 0; w < 8; w++) o += sacc[w * D_ + tid];

    const int idx = b * NCHUNK + c;
    g_pacc[(size_t)idx * D_ + tid] = o;
    if (tid == 0) {
        float Z = 0.0f;
        #pragma unroll
        for (int w = 0; w < 8; w++) Z += s_z[w];
        g_pz[idx] = Z;
    }
}

// ---------------------------------------------------------------------------
// Kernel 3: merge the NCHUNK chunk partials per batch row, write out[b, d].
// All chunks share softmax shift 0 -> merge is a plain sum.
// PDL: launches early, waits for k_chunk's grid in-kernel.
// ---------------------------------------------------------------------------
__global__ void k_merge(float* __restrict__ out) {
    cudaGridDependencySynchronize();

    const int b = blockIdx.x;
    const int tid = threadIdx.x;

    float Z = 0.0f, o = 0.0f;
    #pragma unroll
    for (int c = 0; c < NCHUNK; c++) {
        Z += g_pz[b * NCHUNK + c];
        o += g_pacc[(size_t)(b * NCHUNK + c) * D_ + tid];
    }
    out[b * D_ + tid] = o / Z;
}

// ---------------------------------------------------------------------------
// Inputs (metadata order): 0:x 1:g 2:W 3:Wg 4:b 5:v
// g, Wg, b are provably dead (softmax shift invariance).
// ---------------------------------------------------------------------------
extern "C" void kernel_launch(void* const* d_in, const int* in_sizes, int n_in,
                              void* d_out, int out_size) {
    const float* x = (const float*)d_in[0];
    const float* W = (const float*)d_in[2];
    const float* v = (const float*)d_in[5];
    float* out = (float*)d_out;

    k_wv<<<64, 128>>>(W, v);

    cudaLaunchAttribute pdl[1];
    pdl[0].id = cudaLaunchAttributeProgrammaticStreamSerialization;
    pdl[0].val.programmaticStreamSerializationAllowed = 1;

    cudaLaunchConfig_t cfg1 = {};
    cfg1.gridDim  = dim3(NCHUNK, B_);
    cfg1.blockDim = dim3(256);
    cfg1.stream = 0;
    cfg1.attrs = pdl;
    cfg1.numAttrs = 1;
    cudaLaunchKernelEx(&cfg1, k_chunk, x);

    cudaLaunchConfig_t cfg2 = {};
    cfg2.gridDim  = dim3(B_);
    cfg2.blockDim = dim3(256);
    cfg2.stream = 0;
    cfg2.attrs = pdl;
    cfg2.numAttrs = 1;
    cudaLaunchKernelEx(&cfg2, k_merge, out);
}